// round 2
// baseline (speedup 1.0000x reference)
#include <cuda_runtime.h>
#include <math.h>

#define Bb 8
#define Nn 4096
#define Dd 128
#define TQ 64
#define TK 64

// Scratch for Q/K/V projections (device globals: no allocs allowed)
__device__ float g_Q[Bb*Nn*Dd];
__device__ float g_K[Bb*Nn*Dd];
__device__ float g_V[Bb*Nn*Dd];

// ---------------------------------------------------------------------------
// Projection: Y[m][e] = sum_d X[m][d] * W[e][d]   (torch Linear: x @ W^T)
// grid = (BN/64, 3)  block = 256
// smem: Xs [128][68] d-major, Ws [128][132] d-major
// ---------------------------------------------------------------------------
#define PROJ_SMEM ((128*68 + 128*132) * 4)

__global__ __launch_bounds__(256) void proj_kernel(
    const float* __restrict__ X,
    const float* __restrict__ Wq,
    const float* __restrict__ Wk,
    const float* __restrict__ Wv)
{
    extern __shared__ float sm[];
    float* Xs = sm;             // [128][68]   Xs[d][row]
    float* Ws = sm + 128*68;    // [128][132]  Ws[d][e]

    const float* W;
    float* Y;
    if (blockIdx.y == 0)      { W = Wq; Y = g_Q; }
    else if (blockIdx.y == 1) { W = Wk; Y = g_K; }
    else                      { W = Wv; Y = g_V; }

    const int tid  = threadIdx.x;
    const int row0 = blockIdx.x * 64;

    // Load X tile transposed: 64 rows x 128 d  -> Xs[d][row]
    for (int i = tid; i < 64*32; i += 256) {
        int r  = i >> 5;
        int c4 = (i & 31) << 2;
        float4 v = *(const float4*)(X + (size_t)(row0 + r) * Dd + c4);
        Xs[(c4+0)*68 + r] = v.x;
        Xs[(c4+1)*68 + r] = v.y;
        Xs[(c4+2)*68 + r] = v.z;
        Xs[(c4+3)*68 + r] = v.w;
    }
    // Load W transposed: W[e][d] -> Ws[d][e]
    for (int i = tid; i < 128*32; i += 256) {
        int e  = i >> 5;
        int d4 = (i & 31) << 2;
        float4 v = *(const float4*)(W + e * Dd + d4);
        Ws[(d4+0)*132 + e] = v.x;
        Ws[(d4+1)*132 + e] = v.y;
        Ws[(d4+2)*132 + e] = v.z;
        Ws[(d4+3)*132 + e] = v.w;
    }
    __syncthreads();

    const int ty = tid >> 4;   // 0..15 -> 4 rows each
    const int tx = tid & 15;   // 0..15 -> 8 cols each

    float acc[4][8];
    #pragma unroll
    for (int i = 0; i < 4; i++)
        #pragma unroll
        for (int j = 0; j < 8; j++)
            acc[i][j] = 0.0f;

    #pragma unroll 8
    for (int d = 0; d < 128; d++) {
        float4 a  = *(const float4*)&Xs[d*68  + ty*4];
        float4 b0 = *(const float4*)&Ws[d*132 + tx*8];
        float4 b1 = *(const float4*)&Ws[d*132 + tx*8 + 4];
        float av[4] = {a.x, a.y, a.z, a.w};
        float bv[8] = {b0.x, b0.y, b0.z, b0.w, b1.x, b1.y, b1.z, b1.w};
        #pragma unroll
        for (int i = 0; i < 4; i++)
            #pragma unroll
            for (int j = 0; j < 8; j++)
                acc[i][j] = fmaf(av[i], bv[j], acc[i][j]);
    }

    #pragma unroll
    for (int i = 0; i < 4; i++) {
        int row = row0 + ty*4 + i;
        #pragma unroll
        for (int j = 0; j < 8; j++)
            Y[(size_t)row * Dd + tx*8 + j] = acc[i][j];
    }
}

// ---------------------------------------------------------------------------
// Flash attention, fp32, online softmax. grid = (N/TQ, B), block = 256.
// Per-thread: 4x4 of S (64x64), 4x8 of O (64x128).
// smem: Qs[128][68], Ks[128][68], Vs[64][132], Ps[64][68]
// ---------------------------------------------------------------------------
#define ATTN_SMEM ((128*68 + 128*68 + 64*132 + 64*68) * 4)

__global__ __launch_bounds__(256) void attn_kernel(float* __restrict__ out)
{
    extern __shared__ float sm[];
    float* Qs = sm;                         // [128][68]  Qs[d][qrow]
    float* Ks = Qs + 128*68;                // [128][68]  Ks[d][kcol]
    float* Vs = Ks + 128*68;                // [64][132]  Vs[k][c]
    float* Ps = Vs + 64*132;                // [64][68]   Ps[k][qrow]

    const int tid  = threadIdx.x;
    const int b    = blockIdx.y;
    const int qt   = blockIdx.x;
    const int ty   = tid >> 4;   // 0..15, owns q-rows ty*4..ty*4+3
    const int tx   = tid & 15;   // 0..15

    const size_t qbase = ((size_t)b * Nn + (size_t)qt * TQ) * Dd;

    // Load Q tile transposed
    for (int i = tid; i < TQ*32; i += 256) {
        int r  = i >> 5;
        int c4 = (i & 31) << 2;
        float4 v = *(const float4*)(g_Q + qbase + (size_t)r * Dd + c4);
        Qs[(c4+0)*68 + r] = v.x;
        Qs[(c4+1)*68 + r] = v.y;
        Qs[(c4+2)*68 + r] = v.z;
        Qs[(c4+3)*68 + r] = v.w;
    }

    float m_i[4], l_i[4];
    float o[4][8];
    #pragma unroll
    for (int i = 0; i < 4; i++) {
        m_i[i] = -INFINITY;
        l_i[i] = 0.0f;
        #pragma unroll
        for (int j = 0; j < 8; j++) o[i][j] = 0.0f;
    }

    for (int kt = 0; kt < Nn/TK; kt++) {
        const size_t kbase = ((size_t)b * Nn + (size_t)kt * TK) * Dd;

        // Load K tile (transposed) and V tile (row-major)
        for (int i = tid; i < TK*32; i += 256) {
            int r  = i >> 5;
            int c4 = (i & 31) << 2;
            float4 kv = *(const float4*)(g_K + kbase + (size_t)r * Dd + c4);
            Ks[(c4+0)*68 + r] = kv.x;
            Ks[(c4+1)*68 + r] = kv.y;
            Ks[(c4+2)*68 + r] = kv.z;
            Ks[(c4+3)*68 + r] = kv.w;
            float4 vv = *(const float4*)(g_V + kbase + (size_t)r * Dd + c4);
            *(float4*)&Vs[r*132 + c4] = vv;
        }
        __syncthreads();

        // S = Q K^T : 4x4 per thread
        float s[4][4];
        #pragma unroll
        for (int i = 0; i < 4; i++)
            #pragma unroll
            for (int j = 0; j < 4; j++)
                s[i][j] = 0.0f;

        #pragma unroll 8
        for (int d = 0; d < 128; d++) {
            float4 a  = *(const float4*)&Qs[d*68 + ty*4];
            float4 bb = *(const float4*)&Ks[d*68 + tx*4];
            float av[4] = {a.x, a.y, a.z, a.w};
            float bv[4] = {bb.x, bb.y, bb.z, bb.w};
            #pragma unroll
            for (int i = 0; i < 4; i++)
                #pragma unroll
                for (int j = 0; j < 4; j++)
                    s[i][j] = fmaf(av[i], bv[j], s[i][j]);
        }

        // Online softmax per q-row (16 lanes share a row; reduce via shfl)
        #pragma unroll
        for (int i = 0; i < 4; i++) {
            float tm = fmaxf(fmaxf(s[i][0], s[i][1]), fmaxf(s[i][2], s[i][3]));
            #pragma unroll
            for (int off = 8; off >= 1; off >>= 1)
                tm = fmaxf(tm, __shfl_xor_sync(0xffffffffu, tm, off));
            float mnew = fmaxf(m_i[i], tm);
            float sc   = __expf(m_i[i] - mnew);
            float psum = 0.0f;
            #pragma unroll
            for (int j = 0; j < 4; j++) {
                float p = __expf(s[i][j] - mnew);
                psum += p;
                Ps[(tx*4 + j)*68 + ty*4 + i] = p;
            }
            #pragma unroll
            for (int off = 8; off >= 1; off >>= 1)
                psum += __shfl_xor_sync(0xffffffffu, psum, off);
            l_i[i] = l_i[i] * sc + psum;
            m_i[i] = mnew;
            #pragma unroll
            for (int j = 0; j < 8; j++) o[i][j] *= sc;
        }
        __syncthreads();   // Ps complete

        // O += P V : 4x8 per thread
        #pragma unroll 8
        for (int k = 0; k < TK; k++) {
            float4 a  = *(const float4*)&Ps[k*68 + ty*4];
            float4 b0 = *(const float4*)&Vs[k*132 + tx*8];
            float4 b1 = *(const float4*)&Vs[k*132 + tx*8 + 4];
            float av[4] = {a.x, a.y, a.z, a.w};
            float bv[8] = {b0.x, b0.y, b0.z, b0.w, b1.x, b1.y, b1.z, b1.w};
            #pragma unroll
            for (int i = 0; i < 4; i++)
                #pragma unroll
                for (int j = 0; j < 8; j++)
                    o[i][j] = fmaf(av[i], bv[j], o[i][j]);
        }
        __syncthreads();   // done with Ks/Vs/Ps before next tile load
    }

    // Epilogue: normalize and write
    #pragma unroll
    for (int i = 0; i < 4; i++) {
        float inv = 1.0f / l_i[i];
        size_t row = qbase + (size_t)(ty*4 + i) * Dd;
        #pragma unroll
        for (int j = 0; j < 8; j++)
            out[row + tx*8 + j] = o[i][j] * inv;
    }
}

// ---------------------------------------------------------------------------

extern "C" void kernel_launch(void* const* d_in, const int* in_sizes, int n_in,
                              void* d_out, int out_size)
{
    (void)in_sizes; (void)n_in; (void)out_size;
    const float* X  = (const float*)d_in[0];
    const float* Wq = (const float*)d_in[1];
    const float* Wk = (const float*)d_in[2];
    const float* Wv = (const float*)d_in[3];
    float* out = (float*)d_out;

    cudaFuncSetAttribute(proj_kernel, cudaFuncAttributeMaxDynamicSharedMemorySize, PROJ_SMEM);
    cudaFuncSetAttribute(attn_kernel, cudaFuncAttributeMaxDynamicSharedMemorySize, ATTN_SMEM);

    dim3 pgrid((Bb*Nn)/64, 3);
    proj_kernel<<<pgrid, 256, PROJ_SMEM>>>(X, Wq, Wk, Wv);

    dim3 agrid(Nn/TQ, Bb);
    attn_kernel<<<agrid, 256, ATTN_SMEM>>>(out);
}